// round 1
// baseline (speedup 1.0000x reference)
#include <cuda_runtime.h>
#include <cuda_bf16.h>
#include <cstdint>

#define NN 100000
#define EE 1250000
#define DD 64

// Scratch (allocation-free rule: __device__ globals)
__device__ float g_dis[NN];          // deg accumulation, then deg^{-1/2}
__device__ float g_coef[EE];         // per-edge normalized weight
__device__ float g_h[NN * DD];       // linear output / relu output
__device__ float g_agg[NN * DD];     // aggregation buffer (layer 1) / linear output (layer 2)

// ---------------------------------------------------------------------------
// deg / dis / coef
// ---------------------------------------------------------------------------
__global__ void k_zero_deg() {
    int i = blockIdx.x * blockDim.x + threadIdx.x;
    if (i < NN) g_dis[i] = 0.0f;
}

__global__ void k_deg_acc(const int* __restrict__ dst, const float* __restrict__ w) {
    int e = blockIdx.x * blockDim.x + threadIdx.x;
    if (e < EE) atomicAdd(&g_dis[dst[e]], w[e]);
}

__global__ void k_dis() {
    int i = blockIdx.x * blockDim.x + threadIdx.x;
    if (i < NN) g_dis[i] = rsqrtf(g_dis[i] + 1.0f);
}

__global__ void k_coef(const int* __restrict__ src, const int* __restrict__ dst,
                       const float* __restrict__ w) {
    int e = blockIdx.x * blockDim.x + threadIdx.x;
    if (e < EE) g_coef[e] = g_dis[src[e]] * w[e] * g_dis[dst[e]];
}

// ---------------------------------------------------------------------------
// GEMM: H[n][o] = sum_k X[n][k] * W[o][k]   (X: [n,64], W: [64,64] row-major [out][in])
// 256 threads/block, 32 rows/block. Each thread: 1 row, 8 output cols.
// ---------------------------------------------------------------------------
__global__ void k_gemm(const float* __restrict__ X, const float* __restrict__ W,
                       float* __restrict__ H) {
    __shared__ float Ws[DD][DD];      // Ws[k][o] = W[o][k]
    __shared__ float Xs[32][DD + 1];  // padded for conflict-free column reads

    int tid = threadIdx.x;
    int row0 = blockIdx.x * 32;

    // Load W transposed into shared (one-time)
    for (int idx = tid; idx < DD * DD; idx += 256) {
        int o = idx / DD, k = idx % DD;
        Ws[k][o] = W[o * DD + k];
    }
    // Load 32 rows of X (coalesced)
    for (int idx = tid; idx < 32 * DD; idx += 256) {
        int r = idx / DD, k = idx % DD;
        Xs[r][k] = X[(size_t)(row0 + r) * DD + k];
    }
    __syncthreads();

    int r = tid >> 3;        // 0..31
    int j = (tid & 7) * 8;   // output col base

    float acc[8];
#pragma unroll
    for (int i = 0; i < 8; i++) acc[i] = 0.0f;

#pragma unroll 8
    for (int k = 0; k < DD; k++) {
        float xv = Xs[r][k];
        float4 w0 = *reinterpret_cast<const float4*>(&Ws[k][j]);
        float4 w1 = *reinterpret_cast<const float4*>(&Ws[k][j + 4]);
        acc[0] = fmaf(xv, w0.x, acc[0]);
        acc[1] = fmaf(xv, w0.y, acc[1]);
        acc[2] = fmaf(xv, w0.z, acc[2]);
        acc[3] = fmaf(xv, w0.w, acc[3]);
        acc[4] = fmaf(xv, w1.x, acc[4]);
        acc[5] = fmaf(xv, w1.y, acc[5]);
        acc[6] = fmaf(xv, w1.z, acc[6]);
        acc[7] = fmaf(xv, w1.w, acc[7]);
    }

    float* hp = H + (size_t)(row0 + r) * DD + j;
    float4 o0 = make_float4(acc[0], acc[1], acc[2], acc[3]);
    float4 o1 = make_float4(acc[4], acc[5], acc[6], acc[7]);
    *reinterpret_cast<float4*>(hp) = o0;
    *reinterpret_cast<float4*>(hp + 4) = o1;
}

// ---------------------------------------------------------------------------
// Init aggregation with self-loop term + bias: out[n][c] = h[n][c]*dis[n]^2 + b[c]
// One float4 per thread.
// ---------------------------------------------------------------------------
__global__ void k_init(const float* __restrict__ H, float* __restrict__ OUT,
                       const float* __restrict__ b) {
    int tid = blockIdx.x * blockDim.x + threadIdx.x;   // 0 .. NN*16
    if (tid >= NN * (DD / 4)) return;
    int n = tid >> 4;
    int c = tid & 15;
    float s = g_dis[n];
    s = s * s;
    float4 hv = reinterpret_cast<const float4*>(H)[tid];
    float4 bv = reinterpret_cast<const float4*>(b)[c];
    float4 o;
    o.x = fmaf(hv.x, s, bv.x);
    o.y = fmaf(hv.y, s, bv.y);
    o.z = fmaf(hv.z, s, bv.z);
    o.w = fmaf(hv.w, s, bv.w);
    reinterpret_cast<float4*>(OUT)[tid] = o;
}

// ---------------------------------------------------------------------------
// Edge scatter: OUT[dst[e]] += H[src[e]] * coef[e]
// 16 threads per edge, each handles one float4 chunk, RED.v4.f32 to L2.
// ---------------------------------------------------------------------------
__global__ void k_scatter(const float* __restrict__ H, float* __restrict__ OUT,
                          const int* __restrict__ src, const int* __restrict__ dst) {
    long long tid = (long long)blockIdx.x * blockDim.x + threadIdx.x;
    int e = (int)(tid >> 4);
    if (e >= EE) return;
    int c = (int)(tid & 15);

    int s = src[e];
    int d = dst[e];
    float cf = g_coef[e];

    float4 v = *reinterpret_cast<const float4*>(H + (size_t)s * DD + c * 4);
    v.x *= cf; v.y *= cf; v.z *= cf; v.w *= cf;

    float* p = OUT + (size_t)d * DD + c * 4;
    asm volatile("red.global.add.v4.f32 [%0], {%1,%2,%3,%4};"
                 :: "l"(p), "f"(v.x), "f"(v.y), "f"(v.z), "f"(v.w)
                 : "memory");
}

// ---------------------------------------------------------------------------
// ReLU: Z[i] = max(AGG[i], 0)   (vectorized)
// ---------------------------------------------------------------------------
__global__ void k_relu(const float* __restrict__ AGG, float* __restrict__ Z) {
    int tid = blockIdx.x * blockDim.x + threadIdx.x;
    if (tid >= NN * (DD / 4)) return;
    float4 v = reinterpret_cast<const float4*>(AGG)[tid];
    v.x = fmaxf(v.x, 0.0f);
    v.y = fmaxf(v.y, 0.0f);
    v.z = fmaxf(v.z, 0.0f);
    v.w = fmaxf(v.w, 0.0f);
    reinterpret_cast<float4*>(Z)[tid] = v;
}

// ---------------------------------------------------------------------------
// Launch
// Inputs: 0:x [N,64] f32, 1:edge_index [2,E] i32, 2:edge_weight [E] f32,
//         3:W1 [64,64] f32, 4:b1 [64] f32, 5:W2 [64,64] f32, 6:b2 [64] f32
// Output: [N,64] f32
// ---------------------------------------------------------------------------
extern "C" void kernel_launch(void* const* d_in, const int* in_sizes, int n_in,
                              void* d_out, int out_size) {
    const float* x  = (const float*)d_in[0];
    const int*   ei = (const int*)d_in[1];
    const float* w  = (const float*)d_in[2];
    const float* W1 = (const float*)d_in[3];
    const float* b1 = (const float*)d_in[4];
    const float* W2 = (const float*)d_in[5];
    const float* b2 = (const float*)d_in[6];
    float* out = (float*)d_out;

    const int* src = ei;        // edge_index[0]
    const int* dst = ei + EE;   // edge_index[1]

    float* dis_p;  cudaGetSymbolAddress((void**)&dis_p,  g_dis);
    float* h_p;    cudaGetSymbolAddress((void**)&h_p,    g_h);
    float* agg_p;  cudaGetSymbolAddress((void**)&agg_p,  g_agg);
    (void)dis_p;

    const int T = 256;
    int bN   = (NN + T - 1) / T;
    int bE   = (EE + T - 1) / T;
    int bG   = NN / 32;                    // 3125
    int bI   = (NN * (DD / 4) + T - 1) / T;
    int bS   = (int)(((long long)EE * 16 + T - 1) / T);

    // normalization (shared by both layers)
    k_zero_deg<<<bN, T>>>();
    k_deg_acc<<<bE, T>>>(dst, w);
    k_dis<<<bN, T>>>();
    k_coef<<<bE, T>>>(src, dst, w);

    // layer 1
    k_gemm<<<bG, T>>>(x, W1, h_p);
    k_init<<<bI, T>>>(h_p, agg_p, b1);
    k_scatter<<<bS, T>>>(h_p, agg_p, src, dst);
    k_relu<<<bI, T>>>(agg_p, h_p);

    // layer 2
    k_gemm<<<bG, T>>>(h_p, W2, agg_p);
    k_init<<<bI, T>>>(agg_p, out, b2);
    k_scatter<<<bS, T>>>(agg_p, out, src, dst);
}